// round 3
// baseline (speedup 1.0000x reference)
#include <cuda_runtime.h>
#include <math.h>

#define G_N   20000
#define T_N   1536
#define D_N   512
#define B_N   256
#define K_TOP 32

// ---------- device scratch (static: no allocation in kernel_launch) ----------
__device__ float g_sim[(size_t)G_N * T_N];     // [G, T] similarity scratch (~123 MB)
__device__ float g_tfT[T_N * B_N];             // tf_expr transposed [T, B]
__device__ int   g_tki[G_N * K_TOP];           // top-k indices
__device__ float g_tkw[G_N * K_TOP];           // top-k final weights

// ============================================================================
// Kernel 1: sim[g,t] = (sum_k tg_dec[g,k]*tf_base[t,k]) / sqrt(512)
// Classic smem-tiled SGEMM (NT), BM=128, BN=64, BK=16, 256 threads, 8x4 microtile
// ============================================================================
__global__ __launch_bounds__(256) void sim_gemm(const float* __restrict__ A,
                                                const float* __restrict__ Bm) {
    __shared__ float As[16][132];   // [k][m], padded
    __shared__ float Bs[16][68];    // [k][n], padded

    const int tid = threadIdx.x;
    const int tx = tid & 15;        // 0..15 -> n
    const int ty = tid >> 4;        // 0..15 -> m
    const int bm = blockIdx.y * 128;
    const int bn = blockIdx.x * 64;

    float acc[8][4];
#pragma unroll
    for (int i = 0; i < 8; i++)
#pragma unroll
        for (int j = 0; j < 4; j++) acc[i][j] = 0.f;

    const int lrow = tid >> 2;        // 0..63
    const int lc   = (tid & 3) * 4;   // 0,4,8,12

    for (int k0 = 0; k0 < D_N; k0 += 16) {
        // load A tile (128x16), transpose into As[k][m]
#pragma unroll
        for (int i = 0; i < 2; i++) {
            int row = lrow + i * 64;
            int grow = bm + row;
            float4 v = make_float4(0.f, 0.f, 0.f, 0.f);
            if (grow < G_N)
                v = *(const float4*)(A + (size_t)grow * D_N + k0 + lc);
            As[lc + 0][row] = v.x;
            As[lc + 1][row] = v.y;
            As[lc + 2][row] = v.z;
            As[lc + 3][row] = v.w;
        }
        // load B tile (64x16), transpose into Bs[k][n]
        {
            float4 v = *(const float4*)(Bm + (size_t)(bn + lrow) * D_N + k0 + lc);
            Bs[lc + 0][lrow] = v.x;
            Bs[lc + 1][lrow] = v.y;
            Bs[lc + 2][lrow] = v.z;
            Bs[lc + 3][lrow] = v.w;
        }
        __syncthreads();

#pragma unroll
        for (int kk = 0; kk < 16; kk++) {
            float4 a0 = *(const float4*)&As[kk][ty * 8];
            float4 a1 = *(const float4*)&As[kk][ty * 8 + 4];
            float4 b0 = *(const float4*)&Bs[kk][tx * 4];
            float a[8] = {a0.x, a0.y, a0.z, a0.w, a1.x, a1.y, a1.z, a1.w};
            float b[4] = {b0.x, b0.y, b0.z, b0.w};
#pragma unroll
            for (int i = 0; i < 8; i++)
#pragma unroll
                for (int j = 0; j < 4; j++)
                    acc[i][j] = fmaf(a[i], b[j], acc[i][j]);
        }
        __syncthreads();
    }

    // epilogue: divide by sqrt(512) exactly like the reference (fp32 IEEE div)
    const float sq = 22.627416997969522f;
#pragma unroll
    for (int i = 0; i < 8; i++) {
        int grow = bm + ty * 8 + i;
        if (grow < G_N) {
            float4 o = make_float4(acc[i][0] / sq, acc[i][1] / sq,
                                   acc[i][2] / sq, acc[i][3] / sq);
            *(float4*)(g_sim + (size_t)grow * T_N + bn + tx * 4) = o;
        }
    }
}

// ============================================================================
// block reductions (256 threads)
// ============================================================================
__device__ __forceinline__ float blockMax256(float v) {
    __shared__ float s[8];
#pragma unroll
    for (int o = 16; o > 0; o >>= 1)
        v = fmaxf(v, __shfl_xor_sync(0xffffffffu, v, o));
    if ((threadIdx.x & 31) == 0) s[threadIdx.x >> 5] = v;
    __syncthreads();
    float r = s[0];
#pragma unroll
    for (int i = 1; i < 8; i++) r = fmaxf(r, s[i]);
    __syncthreads();
    return r;
}

__device__ __forceinline__ float blockSum256(float v) {
    __shared__ float s[8];
#pragma unroll
    for (int o = 16; o > 0; o >>= 1)
        v += __shfl_xor_sync(0xffffffffu, v, o);
    if ((threadIdx.x & 31) == 0) s[threadIdx.x >> 5] = v;
    __syncthreads();
    float r = 0.f;
#pragma unroll
    for (int i = 0; i < 8; i++) r += s[i];
    __syncthreads();
    return r;
}

// ============================================================================
// Kernel 2: per-row masked softmax -> top-32 -> renormalize
//   one block (256 thr) per row; each thread owns 6 elements (1536 = 6*256)
//   selection key: (float_bits(e) << 32) | (~idx)  => max value, min index
// ============================================================================
__global__ __launch_bounds__(256) void softmax_topk(const int* __restrict__ mask,
                                                    float* __restrict__ attn_out) {
    const int g   = blockIdx.x;
    const int tid = threadIdx.x;
    const float* srow = g_sim + (size_t)g * T_N;
    const int*   mrow = mask + (size_t)g * T_N;
    float* arow = attn_out + (size_t)g * T_N;

    float sv[6]; int mv[6];
#pragma unroll
    for (int i = 0; i < 6; i++) {
        int t = tid + i * 256;
        sv[i] = srow[t];
        mv[i] = mrow[t];
    }

    float lm = -INFINITY;
#pragma unroll
    for (int i = 0; i < 6; i++)
        if (mv[i]) lm = fmaxf(lm, sv[i]);
    float m = blockMax256(lm);

    if (m == -INFINITY) {  // fully-masked row -> all zeros (matches nan_to_num path)
#pragma unroll
        for (int i = 0; i < 6; i++) arow[tid + i * 256] = 0.f;
        if (tid < K_TOP) {
            g_tkw[g * K_TOP + tid] = 0.f;
            g_tki[g * K_TOP + tid] = 0;
        }
        return;
    }

    float e[6]; float lsum = 0.f;
#pragma unroll
    for (int i = 0; i < 6; i++) {
        e[i] = mv[i] ? expf(sv[i] - m) : 0.f;
        lsum += e[i];
    }
    float Z = blockSum256(lsum);

    unsigned long long key[6];
#pragma unroll
    for (int i = 0; i < 6; i++) {
        unsigned t = (unsigned)(tid + i * 256);
        key[i] = mv[i]
            ? ((((unsigned long long)__float_as_uint(e[i])) << 32) |
               (unsigned long long)(0xFFFFFFFFu - t))
            : 0ull;
    }

    __shared__ unsigned long long skey[8];
    __shared__ float s_e[K_TOP];
    __shared__ int   s_i[K_TOP];
    float outv[6] = {0.f, 0.f, 0.f, 0.f, 0.f, 0.f};

    for (int it = 0; it < K_TOP; it++) {
        unsigned long long lk = 0ull;
#pragma unroll
        for (int i = 0; i < 6; i++)
            if (key[i] > lk) lk = key[i];
#pragma unroll
        for (int o = 16; o > 0; o >>= 1) {
            unsigned long long ok = __shfl_xor_sync(0xffffffffu, lk, o);
            if (ok > lk) lk = ok;
        }
        if ((tid & 31) == 0) skey[tid >> 5] = lk;
        __syncthreads();
        unsigned long long win = skey[0];
#pragma unroll
        for (int i = 1; i < 8; i++)
            if (skey[i] > win) win = skey[i];
        if (tid == 0) {
            s_e[it] = __uint_as_float((unsigned)(win >> 32));
            s_i[it] = win ? (int)(0xFFFFFFFFu - (unsigned)(win & 0xFFFFFFFFull)) : 0;
        }
        if (win) {
#pragma unroll
            for (int i = 0; i < 6; i++) {
                if (key[i] == win) {
                    outv[i] = __uint_as_float((unsigned)(win >> 32));
                    key[i] = 0ull;
                }
            }
        }
        __syncthreads();
    }

    __shared__ float s_den;
    if (tid == 0) {
        float S = 0.f;
#pragma unroll
        for (int it = 0; it < K_TOP; it++) S += s_e[it] / Z;  // sum of attn values
        s_den = S + 1e-8f;
    }
    __syncthreads();
    float den = s_den;

#pragma unroll
    for (int i = 0; i < 6; i++) {
        float a = (outv[i] / Z) / den;   // replicate ref: softmax value, then renorm
        arow[tid + i * 256] = a;
    }
    if (tid < K_TOP) {
        float a = s_e[tid] / Z;
        g_tkw[g * K_TOP + tid] = a / den;
        g_tki[g * K_TOP + tid] = s_i[tid];
    }
}

// ============================================================================
// Kernel 3a: transpose tf_expr [B,T] -> g_tfT [T,B] for coalesced gathers
// ============================================================================
__global__ void transpose_tf(const float* __restrict__ tf) {
    __shared__ float tile[32][33];
    int bx = blockIdx.x * 32;  // T
    int by = blockIdx.y * 32;  // B
#pragma unroll
    for (int r = 0; r < 32; r += 8)
        tile[threadIdx.y + r][threadIdx.x] =
            tf[(size_t)(by + threadIdx.y + r) * T_N + bx + threadIdx.x];
    __syncthreads();
#pragma unroll
    for (int r = 0; r < 32; r += 8)
        g_tfT[(size_t)(bx + threadIdx.y + r) * B_N + by + threadIdx.x] =
            tile[threadIdx.x][threadIdx.y + r];
}

// ============================================================================
// Kernel 3b: sparse combine  out[b,g] = scale * sum_j w[g,j]*tfT[idx[g,j], b]
//   block = 8 g-rows x 256 b-threads; gathers are warp-coalesced 128B lines
// ============================================================================
__global__ __launch_bounds__(256) void combine(const float* __restrict__ scale,
                                               float* __restrict__ outS) {
    const int g0 = blockIdx.x * 8;
    const int b  = threadIdx.x;
    __shared__ int   si[8][K_TOP];
    __shared__ float sw[8][K_TOP];
    {
        int q = threadIdx.x >> 5, j = threadIdx.x & 31;
        si[q][j] = g_tki[(g0 + q) * K_TOP + j];
        sw[q][j] = g_tkw[(g0 + q) * K_TOP + j];
    }
    __syncthreads();

    float acc[8];
#pragma unroll
    for (int q = 0; q < 8; q++) acc[q] = 0.f;

#pragma unroll 4
    for (int j = 0; j < K_TOP; j++) {
#pragma unroll
        for (int q = 0; q < 8; q++)
            acc[q] = fmaf(sw[q][j], g_tfT[si[q][j] * B_N + b], acc[q]);
    }

    float sc = scale[0];
    float4 o0 = make_float4(sc * acc[0], sc * acc[1], sc * acc[2], sc * acc[3]);
    float4 o1 = make_float4(sc * acc[4], sc * acc[5], sc * acc[6], sc * acc[7]);
    float* dst = outS + (size_t)b * G_N + g0;
    *(float4*)dst = o0;
    *(float4*)(dst + 4) = o1;
}

// ============================================================================
// launch
// ============================================================================
extern "C" void kernel_launch(void* const* d_in, const int* in_sizes, int n_in,
                              void* d_out, int out_size) {
    const float* tg_dec     = (const float*)d_in[0];
    const float* tf_base    = (const float*)d_in[1];
    const float* tf_expr    = (const float*)d_in[2];
    const int*   motif_mask = (const int*)d_in[3];
    const float* scale      = (const float*)d_in[4];

    float* out        = (float*)d_out;
    float* out_scalar = out;                          // [B, G]
    float* out_attn   = out + (size_t)B_N * G_N;      // [G, T]

    // transpose tf_expr (independent; needed by combine)
    {
        dim3 blk(32, 8), grd(T_N / 32, B_N / 32);
        transpose_tf<<<grd, blk>>>(tf_expr);
    }
    // sim GEMM
    {
        dim3 blk(256), grd(T_N / 64, (G_N + 127) / 128);
        sim_gemm<<<grd, blk>>>(tg_dec, tf_base);
    }
    // softmax + topk + dense attn write
    softmax_topk<<<G_N, 256>>>(motif_mask, out_attn);
    // sparse weighted combine
    combine<<<G_N / 8, 256>>>(scale, out_scalar);
}

// round 6
// speedup vs baseline: 1.3092x; 1.3092x over previous
#include <cuda_runtime.h>
#include <cuda_bf16.h>
#include <math.h>
#include <stdint.h>
#include <cstdint>

#define G_N   20000
#define T_N   1536
#define D_N   512
#define B_N   256
#define K_TOP 32

// ---------------- device scratch (static: no allocation at runtime) ----------------
__device__ float          g_sim[(size_t)G_N * T_N];   // [G, T] approx similarity
__device__ float          g_tfT[T_N * B_N];           // tf_expr transposed [T, B]
__device__ int            g_tki[G_N * K_TOP];
__device__ float          g_tkw[G_N * K_TOP];
__device__ __nv_bfloat16  g_Ah[(size_t)G_N * D_N];    // tg_dec hi/lo bf16 split
__device__ __nv_bfloat16  g_Al[(size_t)G_N * D_N];
__device__ __nv_bfloat16  g_Bh[(size_t)T_N * D_N];    // tf_base hi/lo bf16 split
__device__ __nv_bfloat16  g_Bl[(size_t)T_N * D_N];

// ============================================================================
// PTX helpers (baseline PTX only — harness ptxas targets plain sm_103,
// which rejects tcgen05/TMEM; mma.sync + cp.async are sm_80+ baseline)
// ============================================================================
__device__ __forceinline__ uint32_t smem_u32(const void* p) {
    uint32_t a;
    asm("{ .reg .u64 t; cvta.to.shared.u64 t, %1; cvt.u32.u64 %0, t; }"
        : "=r"(a) : "l"(p));
    return a;
}
__device__ __forceinline__ void cpa16(uint32_t d, const void* s, bool v) {
    int sz = v ? 16 : 0;
    asm volatile("cp.async.cg.shared.global [%0], [%1], 16, %2;"
                 :: "r"(d), "l"(s), "r"(sz));
}
__device__ __forceinline__ void cpa_commit() {
    asm volatile("cp.async.commit_group;" ::: "memory");
}
__device__ __forceinline__ void cpa_wait2() {
    asm volatile("cp.async.wait_group 2;" ::: "memory");
}
__device__ __forceinline__ void cpa_wait0() {
    asm volatile("cp.async.wait_group 0;" ::: "memory");
}
__device__ __forceinline__ void ldsm_x4(uint32_t& r0, uint32_t& r1,
                                        uint32_t& r2, uint32_t& r3, uint32_t a) {
    asm volatile("ldmatrix.sync.aligned.m8n8.x4.shared.b16 {%0,%1,%2,%3}, [%4];"
                 : "=r"(r0), "=r"(r1), "=r"(r2), "=r"(r3) : "r"(a));
}
__device__ __forceinline__ void mma_bf16(float* d, const uint32_t* a, const uint32_t* b) {
    asm volatile(
        "mma.sync.aligned.m16n8k16.row.col.f32.bf16.bf16.f32 "
        "{%0,%1,%2,%3}, {%4,%5,%6,%7}, {%8,%9}, {%0,%1,%2,%3};"
        : "+f"(d[0]), "+f"(d[1]), "+f"(d[2]), "+f"(d[3])
        : "r"(a[0]), "r"(a[1]), "r"(a[2]), "r"(a[3]), "r"(b[0]), "r"(b[1]));
}

// ============================================================================
// Kernel 0: fp32 -> (bf16 hi, bf16 lo) split of tg_dec and tf_base
// ============================================================================
__global__ void split_bf16(const float* __restrict__ A, const float* __restrict__ Bm) {
    size_t i = (size_t)blockIdx.x * blockDim.x + threadIdx.x;
    const size_t nA = (size_t)G_N * D_N;
    const size_t nB = (size_t)T_N * D_N;
    if (i < nA) {
        float x = A[i];
        __nv_bfloat16 h = __float2bfloat16(x);
        g_Ah[i] = h;
        g_Al[i] = __float2bfloat16(x - __bfloat162float(h));
    } else if (i < nA + nB) {
        size_t j = i - nA;
        float x = Bm[j];
        __nv_bfloat16 h = __float2bfloat16(x);
        g_Bh[j] = h;
        g_Bl[j] = __float2bfloat16(x - __bfloat162float(h));
    }
}

// ============================================================================
// Kernel 1: HMMA bf16x3 GEMM via mma.sync:
//   g_sim[G,T] = (tg_dec @ tf_base^T) / sqrt(512)
//   CTA tile 128x64, BK=32, 3-stage cp.async ring, 8 warps (4m x 2n),
//   warp tile 32x32 (2 m-tiles x 4 n-tiles), 3 HMMA products per k16.
// ============================================================================
#define BK         32
#define AH_OFF     0
#define AL_OFF     8192
#define BH_OFF     16384
#define BL_OFF     20480
#define STG_BYTES  24576
#define NSTAGE     3
#define ALIGN_PAD  256
#define SMEM_DYN   (ALIGN_PAD + NSTAGE * STG_BYTES)
#define K_ITERS    (D_N / BK)   // 16

// rows are 64B (32 bf16); chunk = 16B unit index 0..3, XOR-swizzled by row
__device__ __forceinline__ uint32_t swz(int row, int c) {
    return (uint32_t)(row * 64 + ((c ^ ((row >> 1) & 3)) * 16));
}

__device__ __forceinline__ void load_stage(uint32_t st, int bm, int bn, int k0, int tid) {
    // A: 128 rows x 4 chunks, hi+lo
#pragma unroll
    for (int rep = 0; rep < 2; rep++) {
        int idx = tid + rep * 256;           // 0..511
        int row = idx >> 2, c = idx & 3;
        int grow = bm + row;
        bool va = grow < G_N;
        size_t off = va ? ((size_t)grow * D_N + k0 + c * 8) : 0;
        uint32_t so = swz(row, c);
        cpa16(st + AH_OFF + so, g_Ah + off, va);
        cpa16(st + AL_OFF + so, g_Al + off, va);
    }
    // B: 64 rows x 4 chunks, hi+lo
    {
        int row = tid >> 2, c = tid & 3;
        size_t off = (size_t)(bn + row) * D_N + k0 + c * 8;
        uint32_t so = swz(row, c);
        cpa16(st + BH_OFF + so, g_Bh + off, true);
        cpa16(st + BL_OFF + so, g_Bl + off, true);
    }
}

__global__ __launch_bounds__(256) void gemm_bf16x3() {
    extern __shared__ char sm[];
    uint32_t sb = (smem_u32(sm) + (ALIGN_PAD - 1)) & ~(uint32_t)(ALIGN_PAD - 1);
    const int tid  = threadIdx.x;
    const int wid  = tid >> 5;
    const int lane = tid & 31;
    const int wm   = wid & 3;      // 4 m-warps  -> m offset wm*32
    const int wn   = wid >> 2;     // 2 n-warps  -> n offset wn*32
    const int bm = blockIdx.y * 128;
    const int bn = blockIdx.x * 64;

    float acc[2][4][4];
#pragma unroll
    for (int mt = 0; mt < 2; mt++)
#pragma unroll
        for (int nt = 0; nt < 4; nt++)
#pragma unroll
            for (int r = 0; r < 4; r++) acc[mt][nt][r] = 0.f;

    // prologue: 3 stages in flight
    load_stage(sb + 0 * STG_BYTES, bm, bn, 0, tid);  cpa_commit();
    load_stage(sb + 1 * STG_BYTES, bm, bn, 32, tid); cpa_commit();
    load_stage(sb + 2 * STG_BYTES, bm, bn, 64, tid); cpa_commit();

    // per-lane ldmatrix row/chunk mapping (constant across iterations)
    const int arow = wm * 32 + (lane & 7) + ((lane >> 3) & 1) * 8;  // + mt*16
    const int acs  = (lane >> 4);                                    // + c0
    const int brow = wn * 32 + (lane & 7) + ((lane >> 4) << 3);      // + np*16
    const int bcs  = ((lane >> 3) & 1);                              // + c0

    for (int it = 0; it < K_ITERS; it++) {
        uint32_t st = sb + (uint32_t)(it % NSTAGE) * STG_BYTES;
        if (it < K_ITERS - 3) cpa_wait2(); else cpa_wait0();
        __syncthreads();

#pragma unroll
        for (int ks = 0; ks < 2; ks++) {
            const int c0 = ks * 2;
            uint32_t ah[2][4], al[2][4], bh[2][4], bl[2][4];
            // A fragments: mt=0,1 for hi and lo
#pragma unroll
            for (int mt = 0; mt < 2; mt++) {
                uint32_t ao = swz(arow + mt * 16, c0 + acs);
                ldsm_x4(ah[mt][0], ah[mt][1], ah[mt][2], ah[mt][3], st + AH_OFF + ao);
                ldsm_x4(al[mt][0], al[mt][1], al[mt][2], al[mt][3], st + AL_OFF + ao);
            }
            // B fragments: np=0,1 each covers two n-tiles {r0,r1},{r2,r3}
#pragma unroll
            for (int np = 0; np < 2; np++) {
                uint32_t bo = swz(brow + np * 16, c0 + bcs);
                ldsm_x4(bh[np][0], bh[np][1], bh[np][2], bh[np][3], st + BH_OFF + bo);
                ldsm_x4(bl[np][0], bl[np][1], bl[np][2], bl[np][3], st + BL_OFF + bo);
            }
            // 2m x 4n x 3 products
#pragma unroll
            for (int mt = 0; mt < 2; mt++) {
#pragma unroll
                for (int nt = 0; nt < 4; nt++) {
                    const uint32_t* bhp = &bh[nt >> 1][(nt & 1) * 2];
                    const uint32_t* blp = &bl[nt >> 1][(nt & 1) * 2];
                    mma_bf16(acc[mt][nt], ah[mt], bhp);
                    mma_bf16(acc[mt][nt], ah[mt], blp);
                    mma_bf16(acc[mt][nt], al[mt], bhp);
                }
            }
        }
        __syncthreads();
        if (it + 3 < K_ITERS) {
            load_stage(st, bm, bn, (it + 3) * BK, tid);
            cpa_commit();
        }
    }

    // epilogue: registers -> g_sim with 1/sqrt(512) scale
    const float rs = 0.04419417382415922f;
    const int mrow = (lane >> 2);
    const int ncol = (lane & 3) * 2;
#pragma unroll
    for (int mt = 0; mt < 2; mt++) {
#pragma unroll
        for (int half = 0; half < 2; half++) {   // d0,d1 vs d2,d3 (row +8)
            int m = bm + wm * 32 + mt * 16 + mrow + half * 8;
            if (m < G_N) {
                float* dst = g_sim + (size_t)m * T_N + bn + wn * 32 + ncol;
#pragma unroll
                for (int nt = 0; nt < 4; nt++) {
                    float2 v;
                    v.x = acc[mt][nt][half * 2 + 0] * rs;
                    v.y = acc[mt][nt][half * 2 + 1] * rs;
                    *(float2*)(dst + nt * 8) = v;
                }
            }
        }
    }
}

// ============================================================================
// block reductions (256 threads)
// ============================================================================
__device__ __forceinline__ float blockMax256(float v) {
    __shared__ float s[8];
#pragma unroll
    for (int o = 16; o > 0; o >>= 1)
        v = fmaxf(v, __shfl_xor_sync(0xffffffffu, v, o));
    if ((threadIdx.x & 31) == 0) s[threadIdx.x >> 5] = v;
    __syncthreads();
    float r = s[0];
#pragma unroll
    for (int i = 1; i < 8; i++) r = fmaxf(r, s[i]);
    __syncthreads();
    return r;
}
__device__ __forceinline__ float blockSum256(float v) {
    __shared__ float s[8];
#pragma unroll
    for (int o = 16; o > 0; o >>= 1)
        v += __shfl_xor_sync(0xffffffffu, v, o);
    if ((threadIdx.x & 31) == 0) s[threadIdx.x >> 5] = v;
    __syncthreads();
    float r = 0.f;
#pragma unroll
    for (int i = 0; i < 8; i++) r += s[i];
    __syncthreads();
    return r;
}

// ============================================================================
// Kernel 2: masked softmax -> top-32 (approx) -> contested-band exact fix-up
//           -> renormalize. One 256-thread block per row.
// ============================================================================
__global__ __launch_bounds__(256) void softmax_topk(const int* __restrict__ mask,
                                                    float* __restrict__ attn_out,
                                                    const float* __restrict__ tg,
                                                    const float* __restrict__ tfb) {
    const int g   = blockIdx.x;
    const int tid = threadIdx.x;
    const float* srow = g_sim + (size_t)g * T_N;
    const int*   mrow = mask + (size_t)g * T_N;
    float* arow = attn_out + (size_t)g * T_N;

    float sv[6]; int mv[6];
#pragma unroll
    for (int i = 0; i < 6; i++) {
        int t = tid + i * 256;
        sv[i] = srow[t];
        mv[i] = mrow[t];
    }

    float lm = -INFINITY;
#pragma unroll
    for (int i = 0; i < 6; i++)
        if (mv[i]) lm = fmaxf(lm, sv[i]);
    float m = blockMax256(lm);

    if (m == -INFINITY) {   // fully-masked row
#pragma unroll
        for (int i = 0; i < 6; i++) arow[tid + i * 256] = 0.f;
        if (tid < K_TOP) {
            g_tkw[g * K_TOP + tid] = 0.f;
            g_tki[g * K_TOP + tid] = 0;
        }
        return;
    }

    float e[6]; float lsum = 0.f;
#pragma unroll
    for (int i = 0; i < 6; i++) {
        e[i] = mv[i] ? expf(sv[i] - m) : 0.f;
        lsum += e[i];
    }
    float Z = blockSum256(lsum);

    unsigned long long key[6];
#pragma unroll
    for (int i = 0; i < 6; i++) {
        unsigned t = (unsigned)(tid + i * 256);
        key[i] = mv[i]
            ? ((((unsigned long long)__float_as_uint(e[i])) << 32) |
               (unsigned long long)(0xFFFFFFFFu - t))
            : 0ull;
    }

    __shared__ unsigned long long skey[8];
    __shared__ float s_e[K_TOP];
    float outv[6] = {0.f, 0.f, 0.f, 0.f, 0.f, 0.f};

    for (int it = 0; it < K_TOP; it++) {
        unsigned long long lk = 0ull;
#pragma unroll
        for (int i = 0; i < 6; i++)
            if (key[i] > lk) lk = key[i];
#pragma unroll
        for (int o = 16; o > 0; o >>= 1) {
            unsigned long long ok = __shfl_xor_sync(0xffffffffu, lk, o);
            if (ok > lk) lk = ok;
        }
        if ((tid & 31) == 0) skey[tid >> 5] = lk;
        __syncthreads();
        unsigned long long win = skey[0];
#pragma unroll
        for (int i = 1; i < 8; i++)
            if (skey[i] > win) win = skey[i];
        if (tid == 0) s_e[it] = __uint_as_float((unsigned)(win >> 32));
        if (win) {
#pragma unroll
            for (int i = 0; i < 6; i++) {
                if (key[i] == win) {
                    outv[i] = __uint_as_float((unsigned)(win >> 32));
                    key[i] = 0ull;
                }
            }
        }
        __syncthreads();
    }

    // ---- contested-band exact fix-up (protects selection vs bf16x3 noise) ----
    __shared__ int s_cnt;
    __shared__ int s_ct[32];
    __shared__ unsigned char s_sel[32], s_new[32];
    __shared__ float s_exact[32];
    if (tid == 0) s_cnt = 0;
    __syncthreads();
    float e32 = s_e[K_TOP - 1];
    if (e32 > 0.f) {
        float lo = e32 * (1.f - 3e-4f), hi = e32 * (1.f + 3e-4f);
#pragma unroll
        for (int i = 0; i < 6; i++) {
            if (mv[i] && e[i] >= lo && e[i] <= hi) {
                int p = atomicAdd(&s_cnt, 1);
                if (p < 32) {
                    s_ct[p]  = tid + i * 256;
                    s_sel[p] = (outv[i] != 0.f) ? 1 : 0;
                }
            }
        }
    }
    __syncthreads();
    int nC = s_cnt < 32 ? s_cnt : 32;
    if (nC > 1) {   // rare: exact fp32 recompute + re-rank boundary
        int grp = tid >> 3, l8 = tid & 7;
        int gj = grp < nC ? grp : nC - 1;
        {
            const float* ar = tg + (size_t)g * D_N;
            const float* br = tfb + (size_t)s_ct[gj] * D_N;
            float sacc = 0.f;
            for (int d = l8; d < D_N; d += 8) sacc = fmaf(ar[d], br[d], sacc);
#pragma unroll
            for (int o = 1; o < 8; o <<= 1)
                sacc += __shfl_xor_sync(0xffffffffu, sacc, o);
            if (grp < nC && l8 == 0)
                s_exact[grp] = sacc / 22.627416997969522f;
        }
        __syncthreads();
        if (tid == 0) {
            int slots = 0;
            for (int j = 0; j < nC; j++) { slots += s_sel[j]; s_new[j] = 0; }
            for (int s = 0; s < slots; s++) {
                int best = -1;
                for (int j = 0; j < nC; j++) {
                    if (s_new[j]) continue;
                    if (best < 0 || s_exact[j] > s_exact[best] ||
                        (s_exact[j] == s_exact[best] && s_ct[j] < s_ct[best]))
                        best = j;
                }
                if (best >= 0) s_new[best] = 1;
            }
        }
        __syncthreads();
#pragma unroll
        for (int i = 0; i < 6; i++) {
            int t = tid + i * 256;
            for (int j = 0; j < nC; j++)
                if (s_ct[j] == t) outv[i] = s_new[j] ? e[i] : 0.f;
        }
        __syncthreads();
    }

    // ---- denominator & writes ----
    float ls = 0.f;
#pragma unroll
    for (int i = 0; i < 6; i++) ls += outv[i] / Z;
    float S = blockSum256(ls);
    float den = S + 1e-8f;

#pragma unroll
    for (int i = 0; i < 6; i++)
        arow[tid + i * 256] = (outv[i] / Z) / den;

    // compaction for the sparse combine (order-free: combine sums)
    __shared__ int s_cnt2;
    if (tid < K_TOP) { g_tkw[g * K_TOP + tid] = 0.f; g_tki[g * K_TOP + tid] = 0; }
    if (tid == 0) s_cnt2 = 0;
    __syncthreads();
#pragma unroll
    for (int i = 0; i < 6; i++) {
        if (outv[i] != 0.f) {
            int p = atomicAdd(&s_cnt2, 1);
            if (p < K_TOP) {
                g_tki[g * K_TOP + p] = tid + i * 256;
                g_tkw[g * K_TOP + p] = (outv[i] / Z) / den;
            }
        }
    }
}

// ============================================================================
// Kernel 3a: transpose tf_expr [B,T] -> g_tfT [T,B]
// ============================================================================
__global__ void transpose_tf(const float* __restrict__ tf) {
    __shared__ float tile[32][33];
    int bx = blockIdx.x * 32;
    int by = blockIdx.y * 32;
#pragma unroll
    for (int r = 0; r < 32; r += 8)
        tile[threadIdx.y + r][threadIdx.x] =
            tf[(size_t)(by + threadIdx.y + r) * T_N + bx + threadIdx.x];
    __syncthreads();
#pragma unroll
    for (int r = 0; r < 32; r += 8)
        g_tfT[(size_t)(bx + threadIdx.y + r) * B_N + by + threadIdx.x] =
            tile[threadIdx.x][threadIdx.y + r];
}

// ============================================================================
// Kernel 3b: sparse combine  out[b,g] = scale * sum_j w[g,j]*tfT[idx[g,j], b]
// ============================================================================
__global__ __launch_bounds__(256) void combine(const float* __restrict__ scale,
                                               float* __restrict__ outS) {
    const int g0 = blockIdx.x * 8;
    const int b  = threadIdx.x;
    __shared__ int   si[8][K_TOP];
    __shared__ float sw[8][K_TOP];
    {
        int q = threadIdx.x >> 5, j = threadIdx.x & 31;
        si[q][j] = g_tki[(g0 + q) * K_TOP + j];
        sw[q][j] = g_tkw[(g0 + q) * K_TOP + j];
    }
    __syncthreads();

    float acc[8];
#pragma unroll
    for (int q = 0; q < 8; q++) acc[q] = 0.f;

#pragma unroll 4
    for (int j = 0; j < K_TOP; j++) {
#pragma unroll
        for (int q = 0; q < 8; q++)
            acc[q] = fmaf(sw[q][j], g_tfT[si[q][j] * B_N + b], acc[q]);
    }

    float sc = scale[0];
    float4 o0 = make_float4(sc * acc[0], sc * acc[1], sc * acc[2], sc * acc[3]);
    float4 o1 = make_float4(sc * acc[4], sc * acc[5], sc * acc[6], sc * acc[7]);
    float* dst = outS + (size_t)b * G_N + g0;
    *(float4*)dst = o0;
    *(float4*)(dst + 4) = o1;
}

// ============================================================================
// launch
// ============================================================================
extern "C" void kernel_launch(void* const* d_in, const int* in_sizes, int n_in,
                              void* d_out, int out_size) {
    const float* tg_dec     = (const float*)d_in[0];
    const float* tf_base    = (const float*)d_in[1];
    const float* tf_expr    = (const float*)d_in[2];
    const int*   motif_mask = (const int*)d_in[3];
    const float* scale      = (const float*)d_in[4];

    float* out        = (float*)d_out;
    float* out_scalar = out;                          // [B, G]
    float* out_attn   = out + (size_t)B_N * G_N;      // [G, T]

    cudaFuncSetAttribute(gemm_bf16x3,
                         cudaFuncAttributeMaxDynamicSharedMemorySize, SMEM_DYN);

    // bf16 hi/lo split of both GEMM operands
    {
        size_t total = (size_t)G_N * D_N + (size_t)T_N * D_N;
        int blocks = (int)((total + 255) / 256);
        split_bf16<<<blocks, 256>>>(tg_dec, tf_base);
    }
    // transpose tf_expr (independent; needed by combine)
    {
        dim3 blk(32, 8), grd(T_N / 32, B_N / 32);
        transpose_tf<<<grd, blk>>>(tf_expr);
    }
    // HMMA bf16x3 sim GEMM
    {
        dim3 grd(T_N / 64, (G_N + 127) / 128);   // (24, 157)
        gemm_bf16x3<<<grd, 256, SMEM_DYN>>>();
    }
    // softmax + topk (+ exact boundary fix-up) + dense attn write
    softmax_topk<<<G_N, 256>>>(motif_mask, out_attn, tg_dec, tf_base);
    // sparse weighted combine
    combine<<<G_N / 8, 256>>>(scale, out_scalar);
}